// round 8
// baseline (speedup 1.0000x reference)
#include <cuda_runtime.h>

#define TB 2048   // batch
#define TT 128    // time steps
#define TS 256    // encoder seq len
#define TV 29     // vocab
#define TE 32     // emb dim
#define TH 64     // hidden
#define NB 3      // batches per CTA
#define FCSTRIDE 132 // fc_W row stride (floats); 528B = 16 mod 128 -> conflict-free LDS.128

// enc layout: [NB][TS][64] with 16B-unit swizzle: unit' = unit ^ (s & 15)
// float index = ((j*TS + s) << 6) + ((u ^ (s&15)) << 2) + (h & 3),  u = h >> 2

// smem float-slot offsets
#define OFF_ENC   0
#define SZ_ENC    (NB*TS*TH)               // 49152
#define OFF_FCW   (OFF_ENC + SZ_ENC)       // 49152
#define SZ_FCW    (TV*FCSTRIDE)            // 3828
#define OFF_EMB   (OFF_FCW + SZ_FCW)       // 52980
#define SZ_EMB    (TV*TE)                  // 928
#define OFF_BIAS  (OFF_EMB + SZ_EMB)       // 53908
#define SZ_BIAS   (4*TH)                   // 256
#define OFF_H     (OFF_BIAS + SZ_BIAS)     // 54164
#define SZ_H      (NB*TH)                  // 192
#define OFF_C     (OFF_H + SZ_H)           // 54356
#define OFF_E     (OFF_C + SZ_H)           // 54548
#define SZ_E      (NB*TS)                  // 768
#define OFF_X     (OFF_E + SZ_E)           // 55316  (double-buffered [2][NB][96])
#define SZ_X      (2*NB*96)                // 576
#define OFF_G     (OFF_X + SZ_X)           // 55892
#define SZ_G      (NB*4*TH)                // 768
#define OFF_RED   (OFF_G + SZ_G)           // 56660
#define SZ_RED    (NB*8)                   // 24
#define OFF_FCB   (OFF_RED + SZ_RED)       // 56684 (pad to 32)
#define OFF_Y     (OFF_FCB + 32)           // 56716 (int slots)
#define SZ_Y      (NB*TT)                  // 384
#define SMEM_FLOATS (OFF_Y + SZ_Y)         // 57100
#define SMEM_BYTES  (SMEM_FLOATS * 4)      // 228400 B  (< 232448 cap)

__device__ __forceinline__ float fsig(float x) {
    return __fdividef(1.0f, 1.0f + __expf(-x));
}
__device__ __forceinline__ float ftanh_fast(float x) {
    return 2.0f * __fdividef(1.0f, 1.0f + __expf(-2.0f * x)) - 1.0f;
}

__global__ void __launch_bounds__(256, 1)
decoder_kernel(const int*   __restrict__ y,
               const float* __restrict__ h0,
               const float* __restrict__ c0,
               const float* __restrict__ enc,
               const float* __restrict__ emb_table,
               const float* __restrict__ W_ih,
               const float* __restrict__ W_hh,
               const float* __restrict__ b_ih,
               const float* __restrict__ b_hh,
               const float* __restrict__ fc_W,
               const float* __restrict__ fc_b,
               float* __restrict__ out)
{
    extern __shared__ float sm[];
    float* s_enc  = sm + OFF_ENC;
    float* s_fcw  = sm + OFF_FCW;
    float* s_emb  = sm + OFF_EMB;
    float* s_bias = sm + OFF_BIAS;
    float* s_h    = sm + OFF_H;
    float* s_c    = sm + OFF_C;
    float* s_e    = sm + OFF_E;
    float* s_x    = sm + OFF_X;    // [2][NB][96]
    float* s_g    = sm + OFF_G;    // [NB][256]
    float* s_red  = sm + OFF_RED;  // [NB][8]
    float* s_fcb  = sm + OFF_FCB;
    int*   s_y    = reinterpret_cast<int*>(sm + OFF_Y);

    const int tid  = threadIdx.x;
    const int lane = tid & 31;
    const int wid  = tid >> 5;
    const int b0   = blockIdx.x * NB;
    const int nb   = min(NB, TB - b0);

    // ---- persistent register-resident LSTM weight rows (thread g = tid) ----
    float wih[96];
    float whh[64];
#pragma unroll
    for (int k = 0; k < 96; k += 4) {
        float4 v = *reinterpret_cast<const float4*>(W_ih + tid * 96 + k);
        wih[k] = v.x; wih[k+1] = v.y; wih[k+2] = v.z; wih[k+3] = v.w;
    }
#pragma unroll
    for (int k = 0; k < 64; k += 4) {
        float4 v = *reinterpret_cast<const float4*>(W_hh + tid * 64 + k);
        whh[k] = v.x; whh[k+1] = v.y; whh[k+2] = v.z; whh[k+3] = v.w;
    }

    // ---- one-time SMEM fills ----
    for (int j = 0; j < nb; j++) {
        const float* src = enc + (size_t)(b0 + j) * TS * TH;
        float* dst = s_enc + j * TS * TH;
        for (int i = tid; i < TS * TH; i += 256) {
            int s = i >> 6, h = i & 63;
            int u = h >> 2;
            dst[(s << 6) + (((u ^ (s & 15))) << 2) + (h & 3)] = src[i];
        }
    }
    for (int i = tid; i < TV * 2 * TH; i += 256)
        s_fcw[(i >> 7) * FCSTRIDE + (i & 127)] = fc_W[i];
    for (int i = tid; i < TV * TE; i += 256)
        s_emb[i] = emb_table[i];
    if (tid < 4 * TH) s_bias[tid] = b_ih[tid] + b_hh[tid];
    if (tid < TV)     s_fcb[tid]  = fc_b[tid];
    for (int i = tid; i < nb * TH; i += 256) {
        int j = i >> 6, u = i & 63;
        s_h[i] = h0[(size_t)(b0 + j) * TH + u];
        s_c[i] = c0[(size_t)(b0 + j) * TH + u];
    }
    for (int i = tid; i < nb * TT; i += 256) {
        int j = i >> 7, tt = i & 127;
        s_y[i] = y[(size_t)(b0 + j) * TT + tt];
    }
    __syncthreads();

    // ==================== recurrence ====================
    for (int t = 0; t < TT; t++) {
        const int buf  = t & 1;
        float* xb  = s_x + buf * (NB * 96);        // x for step t
        float* xbp = s_x + (buf ^ 1) * (NB * 96);  // x for step t-1 (logits)

        // ---------- P1: embed(t) + scores(t) (uses h(t-1)) ----------
        if (tid < nb * TE) {
            int j = tid >> 5, e2 = tid & 31;
            int yi = s_y[j * TT + t];
            xb[j * 96 + e2] = s_emb[yi * TE + e2];
        }
        {
            const int sx4 = (tid & 15) << 2;
            float ee[NB];
#pragma unroll
            for (int j = 0; j < NB; j++) {
                ee[j] = 0.0f;
                if (j < nb) {
                    const float* row = s_enc + ((j * TS + tid) << 6);
                    const float* hv  = s_h + j * TH;
                    float a0 = 0.0f, a1 = 0.0f;
#pragma unroll
                    for (int k = 0; k < 16; k += 2) {
                        float4 e0 = *reinterpret_cast<const float4*>(row + (((k    ) << 2) ^ sx4));
                        float4 e1 = *reinterpret_cast<const float4*>(row + (((k + 1) << 2) ^ sx4));
                        float4 h0v = *reinterpret_cast<const float4*>(hv + 4 * k);
                        float4 h1v = *reinterpret_cast<const float4*>(hv + 4 * k + 4);
                        a0 = fmaf(e0.x, h0v.x, a0); a0 = fmaf(e0.y, h0v.y, a0);
                        a0 = fmaf(e0.z, h0v.z, a0); a0 = fmaf(e0.w, h0v.w, a0);
                        a1 = fmaf(e1.x, h1v.x, a1); a1 = fmaf(e1.y, h1v.y, a1);
                        a1 = fmaf(e1.z, h1v.z, a1); a1 = fmaf(e1.w, h1v.w, a1);
                    }
                    float sc = a0 + a1;
                    float ev = __expf(fminf(sc, 80.0f));
                    s_e[j * TS + tid] = ev;
                    ee[j] = ev;
                }
            }
#pragma unroll
            for (int j = 0; j < NB; j++) {
                float v = ee[j];
                v += __shfl_xor_sync(0xffffffffu, v, 16);
                v += __shfl_xor_sync(0xffffffffu, v, 8);
                v += __shfl_xor_sync(0xffffffffu, v, 4);
                v += __shfl_xor_sync(0xffffffffu, v, 2);
                v += __shfl_xor_sync(0xffffffffu, v, 1);
                if (lane == 0) s_red[j * 8 + wid] = v;
            }
        }
        __syncthreads();

        // ---------- P2: context(t) || logits(t-1) ----------
        if (tid < nb * TH) {
            int j = tid >> 6, h = tid & 63;
            float ssum = 0.0f;
#pragma unroll
            for (int w = 0; w < 8; w++) ssum += s_red[j * 8 + w];
            float inv = __fdividef(1.0f, ssum);

            const float* ej = s_e + j * TS;
            const int uh4 = (h >> 2) << 2;
            const int c0i = h & 3;
            const float* eb = s_enc + j * TS * TH + c0i;
            float a0 = 0.0f, a1 = 0.0f;
            for (int s0 = 0; s0 < TS; s0 += 16) {
                const float* ebs = eb + (s0 << 6);
#pragma unroll
                for (int p = 0; p < 16; p += 4) {
                    float4 ev = *reinterpret_cast<const float4*>(ej + s0 + p);
                    a0 = fmaf(ev.x, ebs[((p + 0) << 6) + (uh4 ^ ((p + 0) << 2))], a0);
                    a1 = fmaf(ev.y, ebs[((p + 1) << 6) + (uh4 ^ ((p + 1) << 2))], a1);
                    a0 = fmaf(ev.z, ebs[((p + 2) << 6) + (uh4 ^ ((p + 2) << 2))], a0);
                    a1 = fmaf(ev.w, ebs[((p + 3) << 6) + (uh4 ^ ((p + 3) << 2))], a1);
                }
            }
            xb[j * 96 + TE + h] = (a0 + a1) * inv;
        } else if (t > 0) {
            // logits for step t-1 on otherwise-idle threads (warps 6,7 when nb=3)
            const int tbase = nb * TH;
            const int nthr  = 256 - tbase;
#pragma unroll
            for (int r = 0; r < 2; r++) {
                int idx = (tid - tbase) + r * nthr;
                if (idx < nb * TV) {
                    int j = idx / TV, v = idx - j * TV;
                    const float* wr = s_fcw + v * FCSTRIDE;
                    const float* hh = s_h + j * TH;          // h after step t-1
                    const float* cx = xbp + j * 96 + TE;     // context(t-1)
                    float a0 = s_fcb[v], a1 = 0.0f;
#pragma unroll
                    for (int k = 0; k < 64; k += 4) {
                        float4 w  = *reinterpret_cast<const float4*>(wr + k);
                        float4 hv = *reinterpret_cast<const float4*>(hh + k);
                        a0 = fmaf(w.x, hv.x, a0); a1 = fmaf(w.y, hv.y, a1);
                        a0 = fmaf(w.z, hv.z, a0); a1 = fmaf(w.w, hv.w, a1);
                    }
#pragma unroll
                    for (int k = 0; k < 64; k += 4) {
                        float4 w  = *reinterpret_cast<const float4*>(wr + 64 + k);
                        float4 xv = *reinterpret_cast<const float4*>(cx + k);
                        a0 = fmaf(w.x, xv.x, a0); a1 = fmaf(w.y, xv.y, a1);
                        a0 = fmaf(w.z, xv.z, a0); a1 = fmaf(w.w, xv.w, a1);
                    }
                    out[((size_t)(b0 + j) * TT + (t - 1)) * TV + v] = a0 + a1;
                }
            }
        }
        __syncthreads();

        // ---------- P3: gates (weights in regs, 3 acc chains) ----------
        {
            float acc0 = s_bias[tid];
            float acc1 = acc0, acc2 = acc0;
            const float* x0 = xb;
            const float* x1 = xb + 96;
            const float* x2 = xb + 192;
#pragma unroll
            for (int k = 0; k < 96; k += 4) {
                float4 v0 = *reinterpret_cast<const float4*>(x0 + k);
                float4 v1 = *reinterpret_cast<const float4*>(x1 + k);
                float4 v2 = *reinterpret_cast<const float4*>(x2 + k);
                acc0 = fmaf(wih[k], v0.x, acc0); acc0 = fmaf(wih[k+1], v0.y, acc0);
                acc0 = fmaf(wih[k+2], v0.z, acc0); acc0 = fmaf(wih[k+3], v0.w, acc0);
                acc1 = fmaf(wih[k], v1.x, acc1); acc1 = fmaf(wih[k+1], v1.y, acc1);
                acc1 = fmaf(wih[k+2], v1.z, acc1); acc1 = fmaf(wih[k+3], v1.w, acc1);
                acc2 = fmaf(wih[k], v2.x, acc2); acc2 = fmaf(wih[k+1], v2.y, acc2);
                acc2 = fmaf(wih[k+2], v2.z, acc2); acc2 = fmaf(wih[k+3], v2.w, acc2);
            }
            const float* hp0 = s_h;
            const float* hp1 = s_h + 64;
            const float* hp2 = s_h + 128;
#pragma unroll
            for (int k = 0; k < 64; k += 4) {
                float4 v0 = *reinterpret_cast<const float4*>(hp0 + k);
                float4 v1 = *reinterpret_cast<const float4*>(hp1 + k);
                float4 v2 = *reinterpret_cast<const float4*>(hp2 + k);
                acc0 = fmaf(whh[k], v0.x, acc0); acc0 = fmaf(whh[k+1], v0.y, acc0);
                acc0 = fmaf(whh[k+2], v0.z, acc0); acc0 = fmaf(whh[k+3], v0.w, acc0);
                acc1 = fmaf(whh[k], v1.x, acc1); acc1 = fmaf(whh[k+1], v1.y, acc1);
                acc1 = fmaf(whh[k+2], v1.z, acc1); acc1 = fmaf(whh[k+3], v1.w, acc1);
                acc2 = fmaf(whh[k], v2.x, acc2); acc2 = fmaf(whh[k+1], v2.y, acc2);
                acc2 = fmaf(whh[k+2], v2.z, acc2); acc2 = fmaf(whh[k+3], v2.w, acc2);
            }
            s_g[tid]       = acc0;
            s_g[256 + tid] = acc1;   // garbage if nb<3, never read
            s_g[512 + tid] = acc2;
        }
        __syncthreads();

        // ---------- P4: LSTM cell update ----------
        if (tid < nb * TH) {
            int j = tid >> 6, u = tid & 63;
            const float* gj = s_g + j * 256;
            float gi = gj[u], gf = gj[64 + u], gg = gj[128 + u], go = gj[192 + u];
            float c  = s_c[tid];
            float cn = fsig(gf) * c + fsig(gi) * ftanh_fast(gg);
            float hn = fsig(go) * ftanh_fast(cn);
            s_c[tid] = cn;
            s_h[tid] = hn;
        }
        __syncthreads();
    }

    // ---------- epilogue: logits for t = TT-1 ----------
    if (tid < nb * TV) {
        int j = tid / TV, v = tid - j * TV;
        const float* wr = s_fcw + v * FCSTRIDE;
        const float* hh = s_h + j * TH;
        const float* cx = s_x + ((TT - 1) & 1) * (NB * 96) + j * 96 + TE;
        float a0 = s_fcb[v], a1 = 0.0f;
#pragma unroll
        for (int k = 0; k < 64; k += 4) {
            float4 w  = *reinterpret_cast<const float4*>(wr + k);
            float4 hv = *reinterpret_cast<const float4*>(hh + k);
            a0 = fmaf(w.x, hv.x, a0); a1 = fmaf(w.y, hv.y, a1);
            a0 = fmaf(w.z, hv.z, a0); a1 = fmaf(w.w, hv.w, a1);
        }
#pragma unroll
        for (int k = 0; k < 64; k += 4) {
            float4 w  = *reinterpret_cast<const float4*>(wr + 64 + k);
            float4 xv = *reinterpret_cast<const float4*>(cx + k);
            a0 = fmaf(w.x, xv.x, a0); a1 = fmaf(w.y, xv.y, a1);
            a0 = fmaf(w.z, xv.z, a0); a1 = fmaf(w.w, xv.w, a1);
        }
        out[((size_t)(b0 + j) * TT + (TT - 1)) * TV + v] = a0 + a1;
    }
}

extern "C" void kernel_launch(void* const* d_in, const int* in_sizes, int n_in,
                              void* d_out, int out_size)
{
    const int*   y     = (const int*)d_in[0];
    const float* h0    = (const float*)d_in[1];
    const float* c0    = (const float*)d_in[2];
    const float* enc   = (const float*)d_in[3];
    const float* emb   = (const float*)d_in[4];
    const float* W_ih  = (const float*)d_in[5];
    const float* W_hh  = (const float*)d_in[6];
    const float* b_ih  = (const float*)d_in[7];
    const float* b_hh  = (const float*)d_in[8];
    const float* fc_W  = (const float*)d_in[9];
    const float* fc_b  = (const float*)d_in[10];
    float* out = (float*)d_out;

    cudaFuncSetAttribute(decoder_kernel,
                         cudaFuncAttributeMaxDynamicSharedMemorySize, SMEM_BYTES);

    const int grid = (TB + NB - 1) / NB;  // 683
    decoder_kernel<<<grid, 256, SMEM_BYTES>>>(
        y, h0, c0, enc, emb, W_ih, W_hh, b_ih, b_hh, fc_W, fc_b, out);
}

// round 12
// speedup vs baseline: 1.6273x; 1.6273x over previous
#include <cuda_runtime.h>

#define TB 2048   // batch
#define TT 128    // time steps
#define TS 256    // encoder seq len
#define TV 29     // vocab
#define TE 32     // emb dim
#define TH 64     // hidden
#define NB 3      // batches per CTA
#define ESTRIDE 65   // padded enc row stride (floats): conflict-free rows & cols, LINEAR addressing
#define FCSTRIDE 132 // padded fc_W row stride

// smem float-slot offsets
#define OFF_ENC   0
#define SZ_ENC    (NB*TS*ESTRIDE)          // 49920
#define OFF_FCW   (OFF_ENC + SZ_ENC)       // 49920
#define SZ_FCW    (TV*FCSTRIDE)            // 3828
#define OFF_EMB   (OFF_FCW + SZ_FCW)       // 53748
#define SZ_EMB    (TV*TE)                  // 928
#define OFF_BIAS  (OFF_EMB + SZ_EMB)       // 54676
#define SZ_BIAS   (4*TH)                   // 256
#define OFF_H     (OFF_BIAS + SZ_BIAS)     // 54932
#define SZ_H      (NB*TH)                  // 192
#define OFF_C     (OFF_H + SZ_H)           // 55124
#define OFF_E     (OFF_C + SZ_H)           // 55316
#define SZ_E      (NB*TS)                  // 768
#define OFF_X     (OFF_E + SZ_E)           // 56084  (double-buffered [2][NB][96])
#define SZ_X      (2*NB*96)                // 576
#define OFF_G     (OFF_X + SZ_X)           // 56660
#define SZ_G      (NB*4*TH)                // 768
#define OFF_RED   (OFF_G + SZ_G)           // 57428
#define SZ_RED    (NB*8)                   // 24
#define OFF_FCB   (OFF_RED + SZ_RED)       // 57452 (32 slots)
#define OFF_Y     (OFF_FCB + 32)           // 57484 (int slots)
#define SZ_Y      (NB*TT)                  // 384
#define SMEM_FLOATS (OFF_Y + SZ_Y)         // 57868
#define SMEM_BYTES  (SMEM_FLOATS * 4)      // 231472 B (< 232448 cap)

__device__ __forceinline__ float fsig(float x) {
    return __fdividef(1.0f, 1.0f + __expf(-x));
}
__device__ __forceinline__ float ftanh_fast(float x) {
    return 2.0f * __fdividef(1.0f, 1.0f + __expf(-2.0f * x)) - 1.0f;
}

__global__ void __launch_bounds__(256, 1)
decoder_kernel(const int*   __restrict__ y,
               const float* __restrict__ h0,
               const float* __restrict__ c0,
               const float* __restrict__ enc,
               const float* __restrict__ emb_table,
               const float* __restrict__ W_ih,
               const float* __restrict__ W_hh,
               const float* __restrict__ b_ih,
               const float* __restrict__ b_hh,
               const float* __restrict__ fc_W,
               const float* __restrict__ fc_b,
               float* __restrict__ out)
{
    extern __shared__ float sm[];
    float* s_enc  = sm + OFF_ENC;   // [NB][TS][ESTRIDE]
    float* s_fcw  = sm + OFF_FCW;   // [TV][FCSTRIDE]
    float* s_emb  = sm + OFF_EMB;   // [TV][TE]
    float* s_bias = sm + OFF_BIAS;  // [4H]
    float* s_h    = sm + OFF_H;     // [NB][TH]
    float* s_c    = sm + OFF_C;     // [NB][TH]
    float* s_e    = sm + OFF_E;     // [NB][TS]
    float* s_x    = sm + OFF_X;     // [2][NB][96]
    float* s_g    = sm + OFF_G;     // [NB][256]
    float* s_red  = sm + OFF_RED;   // [NB][8]
    float* s_fcb  = sm + OFF_FCB;   // [TV]
    int*   s_y    = reinterpret_cast<int*>(sm + OFF_Y);  // [NB][TT]

    const int tid  = threadIdx.x;
    const int lane = tid & 31;
    const int wid  = tid >> 5;
    const int b0   = blockIdx.x * NB;
    const int nb   = min(NB, TB - b0);

    // ---- persistent register-resident LSTM weight rows (thread g = tid) ----
    float wih[96];
    float whh[64];
#pragma unroll
    for (int k = 0; k < 96; k += 4) {
        float4 v = *reinterpret_cast<const float4*>(W_ih + tid * 96 + k);
        wih[k] = v.x; wih[k+1] = v.y; wih[k+2] = v.z; wih[k+3] = v.w;
    }
#pragma unroll
    for (int k = 0; k < 64; k += 4) {
        float4 v = *reinterpret_cast<const float4*>(W_hh + tid * 64 + k);
        whh[k] = v.x; whh[k+1] = v.y; whh[k+2] = v.z; whh[k+3] = v.w;
    }

    // ---- one-time SMEM fills ----
    for (int j = 0; j < nb; j++) {
        const float* src = enc + (size_t)(b0 + j) * TS * TH;
        float* dst = s_enc + j * TS * ESTRIDE;
        for (int i = tid; i < TS * TH; i += 256)
            dst[(i >> 6) * ESTRIDE + (i & 63)] = src[i];
    }
    for (int i = tid; i < TV * 2 * TH; i += 256)
        s_fcw[(i >> 7) * FCSTRIDE + (i & 127)] = fc_W[i];
    for (int i = tid; i < TV * TE; i += 256)
        s_emb[i] = emb_table[i];
    if (tid < 4 * TH) s_bias[tid] = b_ih[tid] + b_hh[tid];
    if (tid < TV)     s_fcb[tid]  = fc_b[tid];
    for (int i = tid; i < nb * TH; i += 256) {
        int j = i >> 6, u = i & 63;
        s_h[i] = h0[(size_t)(b0 + j) * TH + u];
        s_c[i] = c0[(size_t)(b0 + j) * TH + u];
    }
    for (int i = tid; i < nb * TT; i += 256) {
        int j = i >> 7, tt = i & 127;
        s_y[i] = y[(size_t)(b0 + j) * TT + tt];
    }
    __syncthreads();

    // ==================== recurrence (4 bars/step) ====================
    for (int t = 0; t < TT; t++) {
        const int buf  = t & 1;
        float* xb  = s_x + buf * (NB * 96);        // x for step t
        float* xbp = s_x + (buf ^ 1) * (NB * 96);  // x for step t-1 (logits)

        // ---------- P1: embed(t) + scores(t) (uses h(t-1)) ----------
        if (tid < nb * TE) {
            int j = tid >> 5, e2 = tid & 31;
            int yi = s_y[j * TT + t];
            xb[j * 96 + e2] = s_emb[yi * TE + e2];
        }
        {
            float ee[NB];
#pragma unroll
            for (int j = 0; j < NB; j++) {
                ee[j] = 0.0f;
                if (j < nb) {
                    const float* er = s_enc + (j * TS + tid) * ESTRIDE;
                    const float* hv = s_h + j * TH;
                    float a0 = 0.0f, a1 = 0.0f;
#pragma unroll
                    for (int h = 0; h < TH; h += 8) {
                        float4 hA = *reinterpret_cast<const float4*>(hv + h);
                        float4 hB = *reinterpret_cast<const float4*>(hv + h + 4);
                        a0 = fmaf(er[h + 0], hA.x, a0);
                        a0 = fmaf(er[h + 1], hA.y, a0);
                        a0 = fmaf(er[h + 2], hA.z, a0);
                        a0 = fmaf(er[h + 3], hA.w, a0);
                        a1 = fmaf(er[h + 4], hB.x, a1);
                        a1 = fmaf(er[h + 5], hB.y, a1);
                        a1 = fmaf(er[h + 6], hB.z, a1);
                        a1 = fmaf(er[h + 7], hB.w, a1);
                    }
                    float sc = a0 + a1;
                    float ev = __expf(fminf(sc, 80.0f));
                    s_e[j * TS + tid] = ev;
                    ee[j] = ev;
                }
            }
#pragma unroll
            for (int j = 0; j < NB; j++) {
                float v = ee[j];
                v += __shfl_xor_sync(0xffffffffu, v, 16);
                v += __shfl_xor_sync(0xffffffffu, v, 8);
                v += __shfl_xor_sync(0xffffffffu, v, 4);
                v += __shfl_xor_sync(0xffffffffu, v, 2);
                v += __shfl_xor_sync(0xffffffffu, v, 1);
                if (lane == 0) s_red[j * 8 + wid] = v;
            }
        }
        __syncthreads();

        // ---------- P2: context(t) (softmax folded) || logits(t-1) ----------
        if (tid < nb * TH) {
            int j = tid >> 6, h = tid & 63;
            float ssum = 0.0f;
#pragma unroll
            for (int w = 0; w < 8; w++) ssum += s_red[j * 8 + w];
            float inv = __fdividef(1.0f, ssum);

            const float* ej   = s_e + j * TS;
            const float* ecol = s_enc + j * TS * ESTRIDE + h;
            float a0 = 0.0f, a1 = 0.0f;
#pragma unroll 8
            for (int s4 = 0; s4 < TS; s4 += 4) {
                float4 ev = *reinterpret_cast<const float4*>(ej + s4);
                a0 = fmaf(ev.x, ecol[(s4 + 0) * ESTRIDE], a0);
                a1 = fmaf(ev.y, ecol[(s4 + 1) * ESTRIDE], a1);
                a0 = fmaf(ev.z, ecol[(s4 + 2) * ESTRIDE], a0);
                a1 = fmaf(ev.w, ecol[(s4 + 3) * ESTRIDE], a1);
            }
            xb[j * 96 + TE + h] = (a0 + a1) * inv;
        } else if (t > 0) {
            // logits for step t-1 on otherwise-idle warps (6,7 when nb=3)
            const int tbase = nb * TH;
            const int nthr  = 256 - tbase;
#pragma unroll
            for (int r = 0; r < 2; r++) {
                int idx = (tid - tbase) + r * nthr;
                if (idx < nb * TV) {
                    int j = idx / TV, v = idx - j * TV;
                    const float* wr = s_fcw + v * FCSTRIDE;
                    const float* hh = s_h + j * TH;          // h after step t-1
                    const float* cx = xbp + j * 96 + TE;     // context(t-1)
                    float a0 = s_fcb[v], a1 = 0.0f;
#pragma unroll
                    for (int k = 0; k < 64; k += 4) {
                        float4 w  = *reinterpret_cast<const float4*>(wr + k);
                        float4 hv = *reinterpret_cast<const float4*>(hh + k);
                        a0 = fmaf(w.x, hv.x, a0); a1 = fmaf(w.y, hv.y, a1);
                        a0 = fmaf(w.z, hv.z, a0); a1 = fmaf(w.w, hv.w, a1);
                    }
#pragma unroll
                    for (int k = 0; k < 64; k += 4) {
                        float4 w  = *reinterpret_cast<const float4*>(wr + 64 + k);
                        float4 xv = *reinterpret_cast<const float4*>(cx + k);
                        a0 = fmaf(w.x, xv.x, a0); a1 = fmaf(w.y, xv.y, a1);
                        a0 = fmaf(w.z, xv.z, a0); a1 = fmaf(w.w, xv.w, a1);
                    }
                    out[((size_t)(b0 + j) * TT + (t - 1)) * TV + v] = a0 + a1;
                }
            }
        }
        __syncthreads();

        // ---------- P3: gates (weights in regs, 3 acc chains) ----------
        {
            float acc0 = s_bias[tid];
            float acc1 = acc0, acc2 = acc0;
            const float* x0 = xb;
            const float* x1 = xb + 96;
            const float* x2 = xb + 192;
#pragma unroll
            for (int k = 0; k < 96; k += 4) {
                float4 v0 = *reinterpret_cast<const float4*>(x0 + k);
                float4 v1 = *reinterpret_cast<const float4*>(x1 + k);
                float4 v2 = *reinterpret_cast<const float4*>(x2 + k);
                acc0 = fmaf(wih[k], v0.x, acc0); acc0 = fmaf(wih[k+1], v0.y, acc0);
                acc0 = fmaf(wih[k+2], v0.z, acc0); acc0 = fmaf(wih[k+3], v0.w, acc0);
                acc1 = fmaf(wih[k], v1.x, acc1); acc1 = fmaf(wih[k+1], v1.y, acc1);
                acc1 = fmaf(wih[k+2], v1.z, acc1); acc1 = fmaf(wih[k+3], v1.w, acc1);
                acc2 = fmaf(wih[k], v2.x, acc2); acc2 = fmaf(wih[k+1], v2.y, acc2);
                acc2 = fmaf(wih[k+2], v2.z, acc2); acc2 = fmaf(wih[k+3], v2.w, acc2);
            }
            const float* hp0 = s_h;
            const float* hp1 = s_h + 64;
            const float* hp2 = s_h + 128;
#pragma unroll
            for (int k = 0; k < 64; k += 4) {
                float4 v0 = *reinterpret_cast<const float4*>(hp0 + k);
                float4 v1 = *reinterpret_cast<const float4*>(hp1 + k);
                float4 v2 = *reinterpret_cast<const float4*>(hp2 + k);
                acc0 = fmaf(whh[k], v0.x, acc0); acc0 = fmaf(whh[k+1], v0.y, acc0);
                acc0 = fmaf(whh[k+2], v0.z, acc0); acc0 = fmaf(whh[k+3], v0.w, acc0);
                acc1 = fmaf(whh[k], v1.x, acc1); acc1 = fmaf(whh[k+1], v1.y, acc1);
                acc1 = fmaf(whh[k+2], v1.z, acc1); acc1 = fmaf(whh[k+3], v1.w, acc1);
                acc2 = fmaf(whh[k], v2.x, acc2); acc2 = fmaf(whh[k+1], v2.y, acc2);
                acc2 = fmaf(whh[k+2], v2.z, acc2); acc2 = fmaf(whh[k+3], v2.w, acc2);
            }
            s_g[tid]       = acc0;
            s_g[256 + tid] = acc1;   // garbage if nb<3, never read
            s_g[512 + tid] = acc2;
        }
        __syncthreads();

        // ---------- P4: LSTM cell update ----------
        if (tid < nb * TH) {
            int j = tid >> 6, u = tid & 63;
            const float* gj = s_g + j * 256;
            float gi = gj[u], gf = gj[64 + u], gg = gj[128 + u], go = gj[192 + u];
            float c  = s_c[tid];
            float cn = fsig(gf) * c + fsig(gi) * ftanh_fast(gg);
            float hn = fsig(go) * ftanh_fast(cn);
            s_c[tid] = cn;
            s_h[tid] = hn;
        }
        __syncthreads();
    }

    // ---------- epilogue: logits for t = TT-1 ----------
    if (tid < nb * TV) {
        int j = tid / TV, v = tid - j * TV;
        const float* wr = s_fcw + v * FCSTRIDE;
        const float* hh = s_h + j * TH;
        const float* cx = s_x + ((TT - 1) & 1) * (NB * 96) + j * 96 + TE;
        float a0 = s_fcb[v], a1 = 0.0f;
#pragma unroll
        for (int k = 0; k < 64; k += 4) {
            float4 w  = *reinterpret_cast<const float4*>(wr + k);
            float4 hv = *reinterpret_cast<const float4*>(hh + k);
            a0 = fmaf(w.x, hv.x, a0); a1 = fmaf(w.y, hv.y, a1);
            a0 = fmaf(w.z, hv.z, a0); a1 = fmaf(w.w, hv.w, a1);
        }
#pragma unroll
        for (int k = 0; k < 64; k += 4) {
            float4 w  = *reinterpret_cast<const float4*>(wr + 64 + k);
            float4 xv = *reinterpret_cast<const float4*>(cx + k);
            a0 = fmaf(w.x, xv.x, a0); a1 = fmaf(w.y, xv.y, a1);
            a0 = fmaf(w.z, xv.z, a0); a1 = fmaf(w.w, xv.w, a1);
        }
        out[((size_t)(b0 + j) * TT + (TT - 1)) * TV + v] = a0 + a1;
    }
}

extern "C" void kernel_launch(void* const* d_in, const int* in_sizes, int n_in,
                              void* d_out, int out_size)
{
    const int*   y     = (const int*)d_in[0];
    const float* h0    = (const float*)d_in[1];
    const float* c0    = (const float*)d_in[2];
    const float* enc   = (const float*)d_in[3];
    const float* emb   = (const float*)d_in[4];
    const float* W_ih  = (const float*)d_in[5];
    const float* W_hh  = (const float*)d_in[6];
    const float* b_ih  = (const float*)d_in[7];
    const float* b_hh  = (const float*)d_in[8];
    const float* fc_W  = (const float*)d_in[9];
    const float* fc_b  = (const float*)d_in[10];
    float* out = (float*)d_out;

    cudaFuncSetAttribute(decoder_kernel,
                         cudaFuncAttributeMaxDynamicSharedMemorySize, SMEM_BYTES);

    const int grid = (TB + NB - 1) / NB;  // 683
    decoder_kernel<<<grid, 256, SMEM_BYTES>>>(
        y, h0, c0, enc, emb, W_ih, W_hh, b_ih, b_hh, fc_W, fc_b, out);
}